// round 4
// baseline (speedup 1.0000x reference)
#include <cuda_runtime.h>
#include <cuda_bf16.h>
#include <math.h>

// Router: N=8192 tokens, C=1024, E=8 experts, top-2, cap=2560.
// Output layout (float32, concatenated): [used_capacity(8) | cb_weight(N*E*cap) | sec_mask(N*E*cap)]

#define C_EMB 1024
#define N_EXP 8
#define TOPK  2
#define MAXN  8192

// Scratch: per-assignment expert index and router prob, priority order i = k*N + n
__device__ int   g_idx [TOPK * MAXN];
__device__ float g_prob[TOPK * MAXN];

// ---------------------------------------------------------------------------
// Kernel A: warp-per-token logits (x[n] . w_g[e]) -> top2 -> 2-way softmax
// ---------------------------------------------------------------------------
__global__ __launch_bounds__(256) void router_gemm_topk(
    const float* __restrict__ x, const float* __restrict__ wg, int N)
{
    __shared__ float s_wg[N_EXP * C_EMB];  // 32 KB
    for (int i = threadIdx.x; i < N_EXP * C_EMB; i += blockDim.x)
        s_wg[i] = wg[i];
    __syncthreads();

    const int warp = threadIdx.x >> 5;
    const int lane = threadIdx.x & 31;
    const int n = blockIdx.x * (blockDim.x >> 5) + warp;
    if (n >= N) return;

    const float4* xr = reinterpret_cast<const float4*>(x + (size_t)n * C_EMB);
    float acc[N_EXP];
#pragma unroll
    for (int e = 0; e < N_EXP; e++) acc[e] = 0.f;

#pragma unroll
    for (int it = 0; it < C_EMB / (32 * 4); it++) {
        float4 v = xr[lane + it * 32];
#pragma unroll
        for (int e = 0; e < N_EXP; e++) {
            float4 w = reinterpret_cast<const float4*>(s_wg + e * C_EMB)[lane + it * 32];
            acc[e] += v.x * w.x + v.y * w.y + v.z * w.z + v.w * w.w;
        }
    }
    // warp reduction of 8 sums
#pragma unroll
    for (int off = 16; off; off >>= 1)
#pragma unroll
        for (int e = 0; e < N_EXP; e++)
            acc[e] += __shfl_xor_sync(0xffffffffu, acc[e], off);

    if (lane == 0) {
        // top-2 (ties -> lower index, matching jax.lax.top_k)
        int e0 = 0; float l0 = acc[0];
#pragma unroll
        for (int e = 1; e < N_EXP; e++) if (acc[e] > l0) { l0 = acc[e]; e0 = e; }
        int e1 = -1; float l1 = -INFINITY;
#pragma unroll
        for (int e = 0; e < N_EXP; e++) if (e != e0 && acc[e] > l1) { l1 = acc[e]; e1 = e; }
        // softmax over the two kept logits
        float t  = __expf(l1 - l0);        // <= 1
        float inv = 1.f / (1.f + t);
        g_idx [n]     = e0;  g_prob[n]     = inv;
        g_idx [N + n] = e1;  g_prob[N + n] = t * inv;
    }
}

// ---------------------------------------------------------------------------
// Kernel B: priority-ordered per-expert rank (prefix count over 2N
// assignments), capacity drop, scatter of nonzeros + used_capacity.
// Single block of 256 threads; each thread owns 2N/256 consecutive items.
// ---------------------------------------------------------------------------
__global__ __launch_bounds__(256) void scan_scatter(
    float* __restrict__ out, int N, int cap)
{
    const int tid = threadIdx.x;
    const int per = (TOPK * N) / 256;   // 64 for N=8192
    const int base_i = tid * per;

    __shared__ int s_hist[256 * N_EXP];
    __shared__ int s_total[N_EXP];

    // Pass 1: local histogram
    int h[N_EXP];
#pragma unroll
    for (int e = 0; e < N_EXP; e++) h[e] = 0;
    for (int j = 0; j < per; j++) h[g_idx[base_i + j]]++;
#pragma unroll
    for (int e = 0; e < N_EXP; e++) s_hist[tid * N_EXP + e] = h[e];
    __syncthreads();

    // Exclusive prefix across threads, one expert per scanning thread
    if (tid < N_EXP) {
        int s = 0;
        for (int t = 0; t < 256; t++) {
            int v = s_hist[t * N_EXP + tid];
            s_hist[t * N_EXP + tid] = s;
            s += v;
        }
        s_total[tid] = s;
    }
    __syncthreads();

    // Pass 2: replay with running counters, scatter kept assignments
    int run[N_EXP];
#pragma unroll
    for (int e = 0; e < N_EXP; e++) run[e] = s_hist[tid * N_EXP + e];

    const size_t cb_base   = N_EXP;                       // after used_capacity
    const size_t mask_off  = (size_t)N * N_EXP * cap;     // sec_mask region offset

    for (int j = 0; j < per; j++) {
        int i = base_i + j;
        int e = g_idx[i];
        int r = run[e]++;
        if (r < cap) {
            int n = i & (N - 1);            // i = k*N + n, N power of 2
            float p = g_prob[i];
            size_t o = cb_base + (size_t)n * (N_EXP * cap) + (size_t)e * cap + r;
            out[o] = p;
            out[o + mask_off] = (p != 0.f) ? 1.f : 0.f;   // sec_mask = bool(cb_weight)
        }
    }

    if (tid < N_EXP) {
        int u = s_total[tid];
        out[tid] = (float)(u < cap ? u : cap);
    }
}

// ---------------------------------------------------------------------------
extern "C" void kernel_launch(void* const* d_in, const int* in_sizes, int n_in,
                              void* d_out, int out_size)
{
    const float* x  = (const float*)d_in[0];
    const float* wg = (const float*)d_in[1];
    int N = in_sizes[0] / C_EMB;      // 8192

    // capacity = floor(2 * 1.25 * N / 8) = (5*N)/16 ; even-pad; min 4
    int cap = (5 * N) / 16;
    cap += (cap & 1);
    if (cap < 4) cap = 4;

    // 1) zero the entire output (poisoned to 0xAA by harness)
    cudaMemsetAsync(d_out, 0, (size_t)out_size * sizeof(float), 0);

    // 2) router logits + top2 + softmax
    int warps_per_block = 256 / 32;
    int blocks = (N + warps_per_block - 1) / warps_per_block;
    router_gemm_topk<<<blocks, 256>>>(x, wg, N);

    // 3) rank scan + capacity drop + scatter
    scan_scatter<<<1, 256>>>((float*)d_out, N, cap);
}

// round 7
// speedup vs baseline: 1.8466x; 1.8466x over previous
#include <cuda_runtime.h>
#include <cuda_bf16.h>
#include <math.h>

// Router: N=8192 tokens, C=1024, E=8 experts, top-2, cap=2560.
// Output (float32): [used_capacity(8) | cb_weight(N*E*cap) | sec_mask(N*E*cap)]

#define C_EMB 1024
#define N_EXP 8
#define TOPK  2
#define MAXN  8192
#define RANK_BLK 256
#define MAX_RBLKS ((TOPK * MAXN) / RANK_BLK)   // 64

// Scratch (priority order i = k*N + n)
__device__ int   g_idx  [TOPK * MAXN];
__device__ float g_prob [TOPK * MAXN];
__device__ int   g_lrank[TOPK * MAXN];              // rank within owning block
__device__ int   g_bhist[MAX_RBLKS * N_EXP];        // per-block expert counts

// ---------------------------------------------------------------------------
// Zero-fill with 16B stores (beats cudaMemsetAsync's observed ~4.7 TB/s)
// ---------------------------------------------------------------------------
__global__ __launch_bounds__(256) void fill_zero(float4* __restrict__ p, long n4)
{
    long i = (long)blockIdx.x * blockDim.x + threadIdx.x;
    const long stride = (long)gridDim.x * blockDim.x;
    const float4 z = make_float4(0.f, 0.f, 0.f, 0.f);
    for (; i < n4; i += stride) p[i] = z;
}

// ---------------------------------------------------------------------------
// Kernel A: warp-per-token logits -> top2 -> 2-way softmax
// ---------------------------------------------------------------------------
__global__ __launch_bounds__(256) void router_gemm_topk(
    const float* __restrict__ x, const float* __restrict__ wg, int N)
{
    __shared__ float s_wg[N_EXP * C_EMB];  // 32 KB
    for (int i = threadIdx.x; i < N_EXP * C_EMB; i += blockDim.x)
        s_wg[i] = wg[i];
    __syncthreads();

    const int warp = threadIdx.x >> 5;
    const int lane = threadIdx.x & 31;
    const int n = blockIdx.x * (blockDim.x >> 5) + warp;
    if (n >= N) return;

    const float4* xr = reinterpret_cast<const float4*>(x + (size_t)n * C_EMB);
    float acc[N_EXP];
#pragma unroll
    for (int e = 0; e < N_EXP; e++) acc[e] = 0.f;

#pragma unroll
    for (int it = 0; it < C_EMB / (32 * 4); it++) {
        float4 v = xr[lane + it * 32];
#pragma unroll
        for (int e = 0; e < N_EXP; e++) {
            float4 w = reinterpret_cast<const float4*>(s_wg + e * C_EMB)[lane + it * 32];
            acc[e] += v.x * w.x + v.y * w.y + v.z * w.z + v.w * w.w;
        }
    }
#pragma unroll
    for (int off = 16; off; off >>= 1)
#pragma unroll
        for (int e = 0; e < N_EXP; e++)
            acc[e] += __shfl_xor_sync(0xffffffffu, acc[e], off);

    if (lane == 0) {
        int e0 = 0; float l0 = acc[0];
#pragma unroll
        for (int e = 1; e < N_EXP; e++) if (acc[e] > l0) { l0 = acc[e]; e0 = e; }
        int e1 = -1; float l1 = -INFINITY;
#pragma unroll
        for (int e = 0; e < N_EXP; e++) if (e != e0 && acc[e] > l1) { l1 = acc[e]; e1 = e; }
        float t   = __expf(l1 - l0);        // <= 1
        float inv = 1.f / (1.f + t);
        g_idx [n]     = e0;  g_prob[n]     = inv;
        g_idx [N + n] = e1;  g_prob[N + n] = t * inv;
    }
}

// ---------------------------------------------------------------------------
// Kernel B: local (within-block) priority rank via warp match + block prefix.
// One item per thread; item order == priority order.
// ---------------------------------------------------------------------------
__global__ __launch_bounds__(RANK_BLK) void rank_local(int total_items)
{
    const int i = blockIdx.x * RANK_BLK + threadIdx.x;
    const int lane = threadIdx.x & 31;
    const int w    = threadIdx.x >> 5;           // 8 warps

    __shared__ int s_whist[8][N_EXP];

    int e = g_idx[i];
    unsigned m = __match_any_sync(0xffffffffu, e);
    int lrank = __popc(m & ((1u << lane) - 1u));

    if (threadIdx.x < 8 * N_EXP) ((int*)s_whist)[threadIdx.x] = 0;
    __syncthreads();
    if (lane == (__ffs(m) - 1)) s_whist[w][e] = __popc(m);
    __syncthreads();

    int woff = 0;
#pragma unroll
    for (int w2 = 0; w2 < 8; w2++)
        if (w2 < w) woff += s_whist[w2][e];
    g_lrank[i] = lrank + woff;

    if (threadIdx.x < N_EXP) {
        int tot = 0;
#pragma unroll
        for (int w2 = 0; w2 < 8; w2++) tot += s_whist[w2][threadIdx.x];
        g_bhist[blockIdx.x * N_EXP + threadIdx.x] = tot;
    }
}

// ---------------------------------------------------------------------------
// Kernel C: per-block global prefix (redundant, cheap) + capacity drop +
// scatter + used_capacity. Same grid shape as Kernel B.
// ---------------------------------------------------------------------------
__global__ __launch_bounds__(RANK_BLK) void scatter(
    float* __restrict__ out, int N, int cap, int nblocks)
{
    __shared__ int s_bh[MAX_RBLKS * N_EXP];
    __shared__ int s_boff[N_EXP];

    for (int t = threadIdx.x; t < nblocks * N_EXP; t += RANK_BLK)
        s_bh[t] = g_bhist[t];
    __syncthreads();

    if (threadIdx.x < N_EXP) {
        int e = threadIdx.x;
        int off = 0;
        for (int b = 0; b < blockIdx.x; b++) off += s_bh[b * N_EXP + e];
        s_boff[e] = off;
        if (blockIdx.x == 0) {
            int tot = 0;
            for (int b = 0; b < nblocks; b++) tot += s_bh[b * N_EXP + e];
            out[e] = (float)(tot < cap ? tot : cap);     // used_capacity
        }
    }
    __syncthreads();

    const int i = blockIdx.x * RANK_BLK + threadIdx.x;
    int e = g_idx[i];
    int r = g_lrank[i] + s_boff[e];
    if (r < cap) {
        int n = i & (N - 1);                 // i = k*N + n, N power of 2
        float p = g_prob[i];
        size_t o = (size_t)N_EXP + (size_t)n * (N_EXP * cap) + (size_t)e * cap + r;
        out[o] = p;
        out[o + (size_t)N * N_EXP * cap] = (p != 0.f) ? 1.f : 0.f;
    }
}

// ---------------------------------------------------------------------------
extern "C" void kernel_launch(void* const* d_in, const int* in_sizes, int n_in,
                              void* d_out, int out_size)
{
    const float* x  = (const float*)d_in[0];
    const float* wg = (const float*)d_in[1];
    int N = in_sizes[0] / C_EMB;      // 8192

    int cap = (5 * N) / 16;           // floor(2 * 1.25 * N / 8)
    cap += (cap & 1);
    if (cap < 4) cap = 4;

    // 1) zero the full output with 16B stores (out_size divisible by 4)
    long n4 = (long)out_size / 4;
    fill_zero<<<148 * 24, 256>>>((float4*)d_out, n4);

    // 2) router logits + top2 + softmax
    int blocks = (N + 7) / 8;
    router_gemm_topk<<<blocks, 256>>>(x, wg, N);

    // 3) parallel priority rank
    int items = TOPK * N;                      // 16384
    int rblocks = items / RANK_BLK;            // 64
    rank_local<<<rblocks, RANK_BLK>>>(items);

    // 4) global prefix + scatter + used_capacity
    scatter<<<rblocks, RANK_BLK>>>((float*)d_out, N, cap, rblocks);
}

// round 8
// speedup vs baseline: 1.9819x; 1.0733x over previous
#include <cuda_runtime.h>
#include <cuda_bf16.h>
#include <math.h>

// Router: N=8192 tokens, C=1024, E=8 experts, top-2, cap=2560.
// Output (float32): [used_capacity(8) | cb_weight(N*E*cap) | sec_mask(N*E*cap)]

#define C_EMB 1024
#define N_EXP 8
#define TOPK  2
#define MAXN  8192
#define RANK_BLK 256
#define MAX_RBLKS ((TOPK * MAXN) / RANK_BLK)   // 64
#define GEMM_BLKS 256                           // gemm blocks inside fused kernel
#define TILE_F4  2048                           // 32KB fill tile per warp-ticket

// Scratch (priority order i = k*N + n)
__device__ int      g_idx  [TOPK * MAXN];
__device__ float    g_prob [TOPK * MAXN];
__device__ int      g_lrank[TOPK * MAXN];
__device__ int      g_bhist[MAX_RBLKS * N_EXP];
__device__ unsigned g_ticket;                   // reset to 0 each launch via memsetAsync

// ---------------------------------------------------------------------------
// Fused kernel: blocks [0, GEMM_BLKS) first compute router logits+top2+softmax
// for their tokens (scratch only — no dependency on the fill), then ALL blocks
// pull 32KB fill tiles from a global ticket counter (per-warp work stealing,
// so gemm latency is absorbed into the memory-bound fill for free).
// ---------------------------------------------------------------------------
__global__ __launch_bounds__(256) void fused_fill_gemm(
    float4* __restrict__ out4, long n4,
    const float* __restrict__ x, const float* __restrict__ wg, int N)
{
    const int lane = threadIdx.x & 31;
    const int w    = threadIdx.x >> 5;

    if (blockIdx.x < GEMM_BLKS) {
        // 256 blocks x 8 warps = 2048 warps; each warp handles 4 tokens
        const int warp_g = blockIdx.x * 8 + w;
        for (int t = 0; t < 4; t++) {
            const int n = warp_g + t * (GEMM_BLKS * 8);
            if (n >= N) break;
            const float4* xr = reinterpret_cast<const float4*>(x + (size_t)n * C_EMB);
            float acc[N_EXP];
#pragma unroll
            for (int e = 0; e < N_EXP; e++) acc[e] = 0.f;
#pragma unroll
            for (int it = 0; it < C_EMB / (32 * 4); it++) {
                float4 v = xr[lane + it * 32];
#pragma unroll
                for (int e = 0; e < N_EXP; e++) {
                    float4 ww = __ldg(reinterpret_cast<const float4*>(wg + e * C_EMB) + lane + it * 32);
                    acc[e] += v.x * ww.x + v.y * ww.y + v.z * ww.z + v.w * ww.w;
                }
            }
#pragma unroll
            for (int off = 16; off; off >>= 1)
#pragma unroll
                for (int e = 0; e < N_EXP; e++)
                    acc[e] += __shfl_xor_sync(0xffffffffu, acc[e], off);

            if (lane == 0) {
                int e0 = 0; float l0 = acc[0];
#pragma unroll
                for (int e = 1; e < N_EXP; e++) if (acc[e] > l0) { l0 = acc[e]; e0 = e; }
                int e1 = -1; float l1 = -INFINITY;
#pragma unroll
                for (int e = 0; e < N_EXP; e++) if (e != e0 && acc[e] > l1) { l1 = acc[e]; e1 = e; }
                float tt  = __expf(l1 - l0);        // <= 1
                float inv = 1.f / (1.f + tt);
                g_idx [n]     = e0;  g_prob[n]     = inv;
                g_idx [N + n] = e1;  g_prob[N + n] = tt * inv;
            }
        }
    }

    // --- fill phase: per-warp ticketed 32KB tiles, streaming stores ---
    const float4 z = make_float4(0.f, 0.f, 0.f, 0.f);
    for (;;) {
        unsigned t;
        if (lane == 0) t = atomicAdd(&g_ticket, 1u);
        t = __shfl_sync(0xffffffffu, t, 0);
        long base = (long)t * TILE_F4;
        if (base >= n4) break;
        long end = base + TILE_F4 < n4 ? base + TILE_F4 : n4;
#pragma unroll 4
        for (long i = base + lane; i < end; i += 32)
            __stcs(&out4[i], z);
    }
}

// ---------------------------------------------------------------------------
// Rank: local (within-chunk) priority rank via warp match + block prefix.
// ---------------------------------------------------------------------------
__global__ __launch_bounds__(RANK_BLK) void rank_local(int total_items)
{
    const int i = blockIdx.x * RANK_BLK + threadIdx.x;
    const int lane = threadIdx.x & 31;
    const int w    = threadIdx.x >> 5;           // 8 warps

    __shared__ int s_whist[8][N_EXP];

    int e = g_idx[i];
    unsigned m = __match_any_sync(0xffffffffu, e);
    int lrank = __popc(m & ((1u << lane) - 1u));

    if (threadIdx.x < 8 * N_EXP) ((int*)s_whist)[threadIdx.x] = 0;
    __syncthreads();
    if (lane == (__ffs(m) - 1)) s_whist[w][e] = __popc(m);
    __syncthreads();

    int woff = 0;
#pragma unroll
    for (int w2 = 0; w2 < 8; w2++)
        if (w2 < w) woff += s_whist[w2][e];
    g_lrank[i] = lrank + woff;

    if (threadIdx.x < N_EXP) {
        int tot = 0;
#pragma unroll
        for (int w2 = 0; w2 < 8; w2++) tot += s_whist[w2][threadIdx.x];
        g_bhist[blockIdx.x * N_EXP + threadIdx.x] = tot;
    }
}

// ---------------------------------------------------------------------------
// Scatter: warp-per-expert shuffle scan over block histograms (no serial loop),
// capacity drop, sparse store, used_capacity.
// ---------------------------------------------------------------------------
__global__ __launch_bounds__(RANK_BLK) void scatter(
    float* __restrict__ out, int N, int cap, int nblocks)
{
    __shared__ int s_boff[N_EXP];
    __shared__ int s_tot [N_EXP];
    const int tid  = threadIdx.x;
    const int lane = tid & 31;
    const int w    = tid >> 5;                   // 8 warps == 8 experts

    {
        // lane l owns blocks 2l and 2l+1 for expert w (nblocks <= 64)
        int b0 = 2 * lane, b1 = 2 * lane + 1;
        int c0 = (b0 < nblocks) ? g_bhist[b0 * N_EXP + w] : 0;
        int c1 = (b1 < nblocks) ? g_bhist[b1 * N_EXP + w] : 0;
        int pair = c0 + c1;
        int scan = pair;                         // inclusive scan of pairs
#pragma unroll
        for (int off = 1; off < 32; off <<= 1) {
            int v = __shfl_up_sync(0xffffffffu, scan, off);
            if (lane >= off) scan += v;
        }
        int excl = scan - pair;                  // sum of blocks [0, 2*lane)
        int b = blockIdx.x;
        int srcl = b >> 1;
        int exclv = __shfl_sync(0xffffffffu, excl, srcl);
        int c0v   = __shfl_sync(0xffffffffu, c0,   srcl);
        int off_b = exclv + ((b & 1) ? c0v : 0); // sum of blocks [0, b)
        int total = __shfl_sync(0xffffffffu, scan, 31);
        if (lane == 0) { s_boff[w] = off_b; s_tot[w] = total; }
    }
    __syncthreads();

    if (blockIdx.x == 0 && tid < N_EXP) {
        int u = s_tot[tid];
        out[tid] = (float)(u < cap ? u : cap);   // used_capacity
    }

    const int i = blockIdx.x * RANK_BLK + tid;
    int e = g_idx[i];
    int r = g_lrank[i] + s_boff[e];
    if (r < cap) {
        int n = i & (N - 1);                     // i = k*N + n, N power of 2
        float p = g_prob[i];
        size_t o = (size_t)N_EXP + (size_t)n * (N_EXP * cap) + (size_t)e * cap + r;
        out[o] = p;
        out[o + (size_t)N * N_EXP * cap] = (p != 0.f) ? 1.f : 0.f;
    }
}

// ---------------------------------------------------------------------------
extern "C" void kernel_launch(void* const* d_in, const int* in_sizes, int n_in,
                              void* d_out, int out_size)
{
    const float* x  = (const float*)d_in[0];
    const float* wg = (const float*)d_in[1];
    int N = in_sizes[0] / C_EMB;      // 8192

    int cap = (5 * N) / 16;           // floor(2 * 1.25 * N / 8)
    cap += (cap & 1);
    if (cap < 4) cap = 4;

    // Reset the fill ticket counter (graph-capturable async memset on symbol)
    void* tick_addr = nullptr;
    cudaGetSymbolAddress(&tick_addr, g_ticket);
    cudaMemsetAsync(tick_addr, 0, sizeof(unsigned), 0);

    // 1) fused: zero-fill whole output + router gemm/top2/softmax (scratch)
    long n4  = (long)out_size / 4;    // out_size divisible by 4 here
    fused_fill_gemm<<<148 * 8, 256>>>((float4*)d_out, n4, x, wg, N);

    // 2) parallel priority rank
    int items   = TOPK * N;           // 16384
    int rblocks = items / RANK_BLK;   // 64
    rank_local<<<rblocks, RANK_BLK>>>(items);

    // 3) shuffle-scan prefix + scatter + used_capacity
    scatter<<<rblocks, RANK_BLK>>>((float*)d_out, N, cap, rblocks);
}